// round 3
// baseline (speedup 1.0000x reference)
#include <cuda_runtime.h>
#include <math_constants.h>

// 5x5 per-channel max (cv2.dilate), SAME padding, (64,384,384,3) fp32.
// Fused dim L = W*C = 1152 floats = 288 float4; block spans full fused row.
// Row-pipelined: vertical 5-max in a register ring, one smem row (double
// buffered) for the cross-thread horizontal 5-max (taps +-3, +-6 fused words).

#define B_    64
#define H_    384
#define L_    1152
#define L4_   288
#define TY    24              // output rows per block
#define NT    288             // threads = float4 per row
#define GUARD 8               // -inf guard words each side
#define SW    (GUARD + L_ + GUARD)   // 1168 words per smem row

__device__ __forceinline__ float4 f4max(float4 a, float4 b) {
    return make_float4(fmaxf(a.x, b.x), fmaxf(a.y, b.y),
                       fmaxf(a.z, b.z), fmaxf(a.w, b.w));
}

__global__ __launch_bounds__(NT, 4)
void dilate5_kernel(const float* __restrict__ in,
                    const int* __restrict__ kptr,
                    float* __restrict__ out)
{
    const int k   = *kptr;
    const int t   = threadIdx.x;
    const int b   = blockIdx.y;
    const int y0  = blockIdx.x * TY;

    if (k == 5) {
        __shared__ float4 bufv[2][SW / 4];          // 16B-aligned rows
        float* buf0 = (float*)bufv[0];
        float* buf1 = (float*)bufv[1];

        // -inf guards for both row buffers (written once, visible after iter-0 sync)
        if (t < 2 * 2 * GUARD) {                    // 32 threads
            const int bb = t >> 4;
            const int j  = t & 15;
            const int ix = (j < GUARD) ? j : (GUARD + L_) + (j - GUARD);
            ((bb ? buf1 : buf0))[ix] = -CUDART_INF_F;
        }

        const float4* inb  = (const float4*)in  + (size_t)b * H_ * L4_;
        float4*       outb = (float4*)      out + (size_t)b * H_ * L4_;
        const float4  NEG  = make_float4(-CUDART_INF_F, -CUDART_INF_F,
                                         -CUDART_INF_F, -CUDART_INF_F);

        // ring holds rows [y-2 .. y+2] for current output row y
        float4 ring[5];
        #pragma unroll
        for (int d = 0; d < 4; ++d) {               // rows y0-2 .. y0+1
            const int y = y0 - 2 + d;
            ring[d] = (y >= 0 && y < H_) ? inb[(size_t)y * L4_ + t] : NEG;
        }
        {   const int y = y0 + 2;
            ring[4] = (y < H_) ? inb[(size_t)y * L4_ + t] : NEG; }

        #pragma unroll
        for (int ty = 0; ty < TY; ++ty) {
            // prefetch row y0+ty+3 (for next iteration) — issue before barrier
            float4 pre;
            {   const int y = y0 + ty + 3;
                pre = (y < H_) ? inb[(size_t)y * L4_ + t] : NEG; }

            // vertical 5-max (slot of row y0+ty+d is (ty+2+d) % 5)
            const float4 vm = f4max(f4max(f4max(ring[(ty + 0) % 5],
                                                ring[(ty + 1) % 5]),
                                          f4max(ring[(ty + 2) % 5],
                                                ring[(ty + 3) % 5])),
                                    ring[(ty + 4) % 5]);

            float* buf = (ty & 1) ? buf1 : buf0;
            *(float4*)(&buf[GUARD + 4 * t]) = vm;
            __syncthreads();

            // horizontal taps around x = 4t (+j): v[x-6..x+9]; own a2 == vm (reg)
            const float2 a0 = *(const float2*)(&buf[GUARD + 4 * t - 6]); // v[x-6],v[x-5]
            const float4 a1 = *(const float4*)(&buf[GUARD + 4 * t - 4]); // v[x-4..x-1]
            const float4 a3 = *(const float4*)(&buf[GUARD + 4 * t + 4]); // v[x+4..x+7]
            const float2 a4 = *(const float2*)(&buf[GUARD + 4 * t + 8]); // v[x+8],v[x+9]

            float4 o;
            // shared core of j=0 and j=3: {v[x-3], v[x], v[x+3], v[x+6]}
            const float tcore = fmaxf(fmaxf(a1.y, vm.x), fmaxf(vm.w, a3.z));
            o.x = fmaxf(a0.x, tcore);                             // + v[x-6]
            o.w = fmaxf(tcore, a4.y);                             // + v[x+9]
            o.y = fmaxf(fmaxf(fmaxf(a0.y, a1.z), vm.y), fmaxf(a3.x, a3.w));
            o.z = fmaxf(fmaxf(fmaxf(a1.x, a1.w), vm.z), fmaxf(a3.y, a4.x));

            outb[(size_t)(y0 + ty) * L4_ + t] = o;

            ring[(ty + 0) % 5] = pre;               // oldest slot <- row y+3
        }
    } else {
        // ---------------- generic fallback (any odd k), SAME padding ----------------
        const int padL = (k - 1) / 2;
        const int C = 3, W = 384;
        #pragma unroll
        for (int j = 0; j < 4; ++j) {
            const int x = 4 * t + j;
            const int w = x / C;
            const int c = x - w * C;
            for (int ty = 0; ty < TY; ++ty) {
                const int oy = y0 + ty;
                float m = -CUDART_INF_F;
                for (int ky = 0; ky < k; ky++) {
                    const int gy = oy - padL + ky;
                    if (gy < 0 || gy >= H_) continue;
                    for (int kx = 0; kx < k; kx++) {
                        const int gw = w - padL + kx;
                        if (gw < 0 || gw >= W) continue;
                        m = fmaxf(m, in[((size_t)b * H_ + gy) * L_ + gw * C + c]);
                    }
                }
                out[((size_t)b * H_ + oy) * L_ + x] = m;
            }
        }
    }
}

extern "C" void kernel_launch(void* const* d_in, const int* in_sizes, int n_in,
                              void* d_out, int out_size)
{
    const float* images = (const float*)d_in[0];
    const int*   kptr   = (const int*)d_in[1];
    float*       out    = (float*)d_out;

    dim3 grid(H_ / TY, B_);    // 16 x 64
    dim3 block(NT);            // 288
    dilate5_kernel<<<grid, block>>>(images, kptr, out);
}